// round 4
// baseline (speedup 1.0000x reference)
#include <cuda_runtime.h>

// GRUConv3d: 8-direction 3D GRU with 3 conv gates per direction.
// Shapes: x (2,32,32,32,32) f32; W* (8,32,32,3,3,3); b* (8,32); h0 (8,32).
// out (2,32,32,32,32) f32.
//
// Pipeline:
//   conv_kernel    : all 8 dirs x 3 gates -> g_hb (linear+bias), g_z/g_s (sigmoid)
//   scan_kernel    : diagonal GRU recurrence per dir; overwrites g_hb with O*s
//   combine_kernel : out = sum over dirs of contrib

#define NDIR 8
#define B_   2
#define C_   32
#define SPAT 32768                      // 32*32*32
#define NT   (NDIR * B_ * C_ * SPAT)    // 16,777,216 floats per tensor

__device__ float g_hb[NT];   // conv-h output, later overwritten with contrib = O*s
__device__ float g_z [NT];   // sigmoid(conv-z)
__device__ float g_s [NT];   // sigmoid(conv-s)

// ---------------------------------------------------------------------------
// Conv kernel: each block handles (dir n, batch b, depth d, h-tile of 8 rows),
// producing 96 output channels (3 gates x 32 cout) over 8h x 32w positions.
// Register blocking: thread = (warp -> 4 couts) x (lane -> w column, 8 h rows).
// cin is chunked by 4 so that Xs + Wsm fit in static (<48KB) shared memory.
// ---------------------------------------------------------------------------
__global__ __launch_bounds__(256, 2)
void conv_kernel(const float* __restrict__ x,
                 const float* __restrict__ Wh, const float* __restrict__ bh,
                 const float* __restrict__ Wz, const float* __restrict__ bz,
                 const float* __restrict__ Ws, const float* __restrict__ bs)
{
    __shared__ float Xs[4 * 3 * 10 * 34];   // [ci4][td][hh 0..9][ww 0..33] = 16320 B
    __shared__ float Wsm[32 * 4 * 27];      // [co][ci4][tap]               = 13824 B

    const int bi  = blockIdx.x;
    const int n   = bi >> 8;          // direction
    const int rem = bi & 255;
    const int b   = rem >> 7;
    const int d   = (rem >> 2) & 31;
    const int h0  = (rem & 3) * 8;

    const int tid = threadIdx.x;
    const int cg  = tid >> 5;         // warp id: co base = cg*4
    const int sg  = tid & 31;         // w coordinate

    const float* xb = x + (size_t)b * (32 * SPAT);

    for (int gate = 0; gate < 3; gate++) {
        const float* Wg = (gate == 0) ? Wh : (gate == 1) ? Wz : Ws;

        float acc[4][8];
        #pragma unroll
        for (int c = 0; c < 4; c++)
            #pragma unroll
            for (int r = 0; r < 8; r++) acc[c][r] = 0.f;

        for (int cc = 0; cc < 8; cc++) {          // cin chunks of 4
            __syncthreads();
            // ---- stage x chunk into smem (zero-padded halo in d,h,w) ----
            for (int idx = tid; idx < 4 * 3 * 10 * 34; idx += 256) {
                int ww = idx % 34;
                int t  = idx / 34;
                int hh = t % 10; t /= 10;
                int td = t % 3;
                int ci = t / 3;
                int gd = d - 1 + td;
                int gh = h0 - 1 + hh;
                int gw = ww - 1;
                float v = 0.f;
                if ((unsigned)gd < 32u && (unsigned)gh < 32u && (unsigned)gw < 32u)
                    v = xb[(size_t)(cc * 4 + ci) * SPAT + gd * 1024 + gh * 32 + gw];
                Xs[idx] = v;
            }
            // ---- stage weight chunk: [co 0..31][ci4][tap 0..26] ----
            for (int idx = tid; idx < 32 * 4 * 27; idx += 256) {
                int tap = idx % 27;
                int t   = idx / 27;
                int ci  = t & 3;
                int co  = t >> 2;
                Wsm[idx] = Wg[(((size_t)n * 32 + co) * 32 + (cc * 4 + ci)) * 27 + tap];
            }
            __syncthreads();

            // ---- compute: 4 cin x 27 taps x (4 cout x 8 h) FMAs ----
            for (int ci = 0; ci < 4; ci++) {
                const float* Xp = Xs + ci * (3 * 10 * 34);
                const float* Wp = Wsm + (cg * 4) * (4 * 27) + ci * 27;
                for (int td = 0; td < 3; td++) {
                    for (int th = 0; th < 3; th++) {
                        const float* xr = Xp + td * 340 + th * 34 + sg;
                        const float* wr = Wp + (td * 3 + th) * 3;
                        #pragma unroll
                        for (int tw = 0; tw < 3; tw++) {
                            float w0 = wr[0 * 108 + tw];
                            float w1 = wr[1 * 108 + tw];
                            float w2 = wr[2 * 108 + tw];
                            float w3 = wr[3 * 108 + tw];
                            #pragma unroll
                            for (int r = 0; r < 8; r++) {
                                float xv = xr[r * 34 + tw];
                                acc[0][r] = fmaf(w0, xv, acc[0][r]);
                                acc[1][r] = fmaf(w1, xv, acc[1][r]);
                                acc[2][r] = fmaf(w2, xv, acc[2][r]);
                                acc[3][r] = fmaf(w3, xv, acc[3][r]);
                            }
                        }
                    }
                }
            }
        }

        // ---- epilogue: bias (+ sigmoid for z,s gates), write scratch ----
        const float* bg = (gate == 0) ? bh : (gate == 1) ? bz : bs;
        float* og       = (gate == 0) ? g_hb : (gate == 1) ? g_z : g_s;
        #pragma unroll
        for (int c = 0; c < 4; c++) {
            int   co   = cg * 4 + c;
            float bias = bg[n * 32 + co];
            float* op  = og + ((size_t)((n * 2 + b) * 32 + co)) * SPAT
                            + d * 1024 + h0 * 32 + sg;
            #pragma unroll
            for (int r = 0; r < 8; r++) {
                float v = acc[c][r] + bias;
                if (gate > 0) v = 1.f / (1.f + __expf(-v));
                op[r * 32] = v;
            }
        }
    }
}

// ---------------------------------------------------------------------------
// Scan kernel: one thread per diagonal chain. Chain starts live on the 3
// "entry" faces of the cube for direction (di,dj,dk). Each cell is visited
// exactly once; contrib = O*s overwrites g_hb in place (no races).
// 2977 chains per (dir,b,c) -> 3 blocks of 1024 threads.
// ---------------------------------------------------------------------------
__global__ void scan_kernel(const float* __restrict__ h0)
{
    int bid  = blockIdx.x;
    int part = bid % 3;
    int t    = bid / 3;
    int c = t & 31; t >>= 5;
    int b = t & 1;
    int n = t >> 1;

    int cid = part * 1024 + threadIdx.x;
    if (cid >= 2977) return;

    const int di = (n & 4) ? 1 : -1;
    const int dj = (n & 2) ? 1 : -1;
    const int dk = (n & 1) ? 1 : -1;
    const int si = (di == 1) ? 0 : 31;
    const int sj = (dj == 1) ? 0 : 31;
    const int sk = (dk == 1) ? 0 : 31;

    int i0, j0, k0;
    if (cid < 1024) {                       // face i == si (1024 chains)
        i0 = si; j0 = cid >> 5; k0 = cid & 31;
    } else if (cid < 2016) {                // face j == sj, i != si (992)
        int q = cid - 1024;
        j0 = sj;
        int ii = q >> 5;
        i0 = (di == 1) ? ii + 1 : ii;
        k0 = q & 31;
    } else {                                // face k == sk, i != si, j != sj (961)
        int q = cid - 2016;
        k0 = sk;
        int ii = q / 31;
        int jj = q % 31;
        i0 = (di == 1) ? ii + 1 : ii;
        j0 = (dj == 1) ? jj + 1 : jj;
    }

    int li = (di == 1) ? 32 - i0 : i0 + 1;
    int lj = (dj == 1) ? 32 - j0 : j0 + 1;
    int lk = (dk == 1) ? 32 - k0 : k0 + 1;
    int L  = min(li, min(lj, lk));

    const size_t base = ((size_t)((n * 2 + b) * 32 + c)) << 15;
    int idx  = i0 * 1024 + j0 * 32 + k0;
    int step = di * 1024 + dj * 32 + dk;

    float h = h0[n * 32 + c];
    for (int s = 0; s < L; s++, idx += step) {
        float zv = g_z [base + idx];
        float hv = g_hb[base + idx];
        float sv = g_s [base + idx];
        h = fmaf(zv, hv - h, h);            // z*hb + (1-z)*h
        g_hb[base + idx] = h * sv;          // contrib, in place
    }
}

// ---------------------------------------------------------------------------
// Combine: out[b,c,spatial] = sum over 8 dirs of contrib
// ---------------------------------------------------------------------------
__global__ void combine_kernel(float* __restrict__ out)
{
    int p = blockIdx.x * blockDim.x + threadIdx.x;
    if (p >= B_ * C_ * SPAT) return;
    int sp = p & (SPAT - 1);
    int t  = p >> 15;
    int c  = t & 31;
    int b  = t >> 5;
    float s = 0.f;
    #pragma unroll
    for (int n = 0; n < 8; n++)
        s += g_hb[((size_t)((n * 2 + b) * 32 + c) << 15) + sp];
    out[p] = s;
}

extern "C" void kernel_launch(void* const* d_in, const int* in_sizes, int n_in,
                              void* d_out, int out_size)
{
    const float* x  = (const float*)d_in[0];
    const float* Wh = (const float*)d_in[1];
    const float* bh = (const float*)d_in[2];
    const float* Wz = (const float*)d_in[3];
    const float* bz = (const float*)d_in[4];
    const float* Ws = (const float*)d_in[5];
    const float* bs = (const float*)d_in[6];
    const float* h0 = (const float*)d_in[7];
    float* out = (float*)d_out;

    conv_kernel<<<2048, 256>>>(x, Wh, bh, Wz, bz, Ws, bs);
    scan_kernel<<<1536, 1024>>>(h0);
    combine_kernel<<<(B_ * C_ * SPAT + 255) / 256, 256>>>(out);
}

// round 5
// speedup vs baseline: 1.0015x; 1.0015x over previous
#include <cuda_runtime.h>

// GRUConv3d: 8-direction 3D GRU with 3 conv gates per direction.
// Shapes: x (2,32,32,32,32) f32; W* (8,32,32,3,3,3); b* (8,32); h0 (8,32).
// out (2,32,32,32,32) f32.
//
// Pipeline:
//   conv_kernel    : all 8 dirs x 3 gates -> g_hb (linear+bias), g_z/g_s (sigmoid)
//   scan_kernel    : diagonal GRU recurrence per dir; overwrites g_hb with O*s
//   combine_kernel : out = sum over dirs of contrib

#define NDIR 8
#define B_   2
#define C_   32
#define SPAT 32768                      // 32*32*32
#define NT   (NDIR * B_ * C_ * SPAT)    // 16,777,216 floats per tensor

__device__ float g_hb[NT];   // conv-h output, later overwritten with contrib = O*s
__device__ float g_z [NT];   // sigmoid(conv-z)
__device__ float g_s [NT];   // sigmoid(conv-s)

// ---------------------------------------------------------------------------
// Conv kernel: each block handles (dir n, batch b, depth d, h-tile of 8 rows),
// producing 96 output channels (3 gates x 32 cout) over 8h x 32w positions.
// Register blocking: thread = (warp -> 4 couts) x (lane -> w column, 8 h rows).
// cin is chunked by 4 so that Xs + Wsm fit in static (<48KB) shared memory.
// ---------------------------------------------------------------------------
__global__ __launch_bounds__(256, 2)
void conv_kernel(const float* __restrict__ x,
                 const float* __restrict__ Wh, const float* __restrict__ bh,
                 const float* __restrict__ Wz, const float* __restrict__ bz,
                 const float* __restrict__ Ws, const float* __restrict__ bs)
{
    __shared__ float Xs[4 * 3 * 10 * 34];   // [ci4][td][hh 0..9][ww 0..33] = 16320 B
    __shared__ float Wsm[32 * 4 * 27];      // [co][ci4][tap]               = 13824 B

    const int bi  = blockIdx.x;
    const int n   = bi >> 8;          // direction
    const int rem = bi & 255;
    const int b   = rem >> 7;
    const int d   = (rem >> 2) & 31;
    const int h0  = (rem & 3) * 8;

    const int tid = threadIdx.x;
    const int cg  = tid >> 5;         // warp id: co base = cg*4
    const int sg  = tid & 31;         // w coordinate

    const float* xb = x + (size_t)b * (32 * SPAT);

    for (int gate = 0; gate < 3; gate++) {
        const float* Wg = (gate == 0) ? Wh : (gate == 1) ? Wz : Ws;

        float acc[4][8];
        #pragma unroll
        for (int c = 0; c < 4; c++)
            #pragma unroll
            for (int r = 0; r < 8; r++) acc[c][r] = 0.f;

        for (int cc = 0; cc < 8; cc++) {          // cin chunks of 4
            __syncthreads();
            // ---- stage x chunk into smem (zero-padded halo in d,h,w) ----
            for (int idx = tid; idx < 4 * 3 * 10 * 34; idx += 256) {
                int ww = idx % 34;
                int t  = idx / 34;
                int hh = t % 10; t /= 10;
                int td = t % 3;
                int ci = t / 3;
                int gd = d - 1 + td;
                int gh = h0 - 1 + hh;
                int gw = ww - 1;
                float v = 0.f;
                if ((unsigned)gd < 32u && (unsigned)gh < 32u && (unsigned)gw < 32u)
                    v = xb[(size_t)(cc * 4 + ci) * SPAT + gd * 1024 + gh * 32 + gw];
                Xs[idx] = v;
            }
            // ---- stage weight chunk: [co 0..31][ci4][tap 0..26] ----
            for (int idx = tid; idx < 32 * 4 * 27; idx += 256) {
                int tap = idx % 27;
                int t   = idx / 27;
                int ci  = t & 3;
                int co  = t >> 2;
                Wsm[idx] = Wg[(((size_t)n * 32 + co) * 32 + (cc * 4 + ci)) * 27 + tap];
            }
            __syncthreads();

            // ---- compute: 4 cin x 27 taps x (4 cout x 8 h) FMAs ----
            for (int ci = 0; ci < 4; ci++) {
                const float* Xp = Xs + ci * (3 * 10 * 34);
                const float* Wp = Wsm + (cg * 4) * (4 * 27) + ci * 27;
                for (int td = 0; td < 3; td++) {
                    for (int th = 0; th < 3; th++) {
                        const float* xr = Xp + td * 340 + th * 34 + sg;
                        const float* wr = Wp + (td * 3 + th) * 3;
                        #pragma unroll
                        for (int tw = 0; tw < 3; tw++) {
                            float w0 = wr[0 * 108 + tw];
                            float w1 = wr[1 * 108 + tw];
                            float w2 = wr[2 * 108 + tw];
                            float w3 = wr[3 * 108 + tw];
                            #pragma unroll
                            for (int r = 0; r < 8; r++) {
                                float xv = xr[r * 34 + tw];
                                acc[0][r] = fmaf(w0, xv, acc[0][r]);
                                acc[1][r] = fmaf(w1, xv, acc[1][r]);
                                acc[2][r] = fmaf(w2, xv, acc[2][r]);
                                acc[3][r] = fmaf(w3, xv, acc[3][r]);
                            }
                        }
                    }
                }
            }
        }

        // ---- epilogue: bias (+ sigmoid for z,s gates), write scratch ----
        const float* bg = (gate == 0) ? bh : (gate == 1) ? bz : bs;
        float* og       = (gate == 0) ? g_hb : (gate == 1) ? g_z : g_s;
        #pragma unroll
        for (int c = 0; c < 4; c++) {
            int   co   = cg * 4 + c;
            float bias = bg[n * 32 + co];
            float* op  = og + ((size_t)((n * 2 + b) * 32 + co)) * SPAT
                            + d * 1024 + h0 * 32 + sg;
            #pragma unroll
            for (int r = 0; r < 8; r++) {
                float v = acc[c][r] + bias;
                if (gate > 0) v = 1.f / (1.f + __expf(-v));
                op[r * 32] = v;
            }
        }
    }
}

// ---------------------------------------------------------------------------
// Scan kernel: one thread per diagonal chain. Chain starts live on the 3
// "entry" faces of the cube for direction (di,dj,dk). Each cell is visited
// exactly once; contrib = O*s overwrites g_hb in place (no races).
// 2977 chains per (dir,b,c) -> 3 blocks of 1024 threads.
// ---------------------------------------------------------------------------
__global__ void scan_kernel(const float* __restrict__ h0)
{
    int bid  = blockIdx.x;
    int part = bid % 3;
    int t    = bid / 3;
    int c = t & 31; t >>= 5;
    int b = t & 1;
    int n = t >> 1;

    int cid = part * 1024 + threadIdx.x;
    if (cid >= 2977) return;

    const int di = (n & 4) ? 1 : -1;
    const int dj = (n & 2) ? 1 : -1;
    const int dk = (n & 1) ? 1 : -1;
    const int si = (di == 1) ? 0 : 31;
    const int sj = (dj == 1) ? 0 : 31;
    const int sk = (dk == 1) ? 0 : 31;

    int i0, j0, k0;
    if (cid < 1024) {                       // face i == si (1024 chains)
        i0 = si; j0 = cid >> 5; k0 = cid & 31;
    } else if (cid < 2016) {                // face j == sj, i != si (992)
        int q = cid - 1024;
        j0 = sj;
        int ii = q >> 5;
        i0 = (di == 1) ? ii + 1 : ii;
        k0 = q & 31;
    } else {                                // face k == sk, i != si, j != sj (961)
        int q = cid - 2016;
        k0 = sk;
        int ii = q / 31;
        int jj = q % 31;
        i0 = (di == 1) ? ii + 1 : ii;
        j0 = (dj == 1) ? jj + 1 : jj;
    }

    int li = (di == 1) ? 32 - i0 : i0 + 1;
    int lj = (dj == 1) ? 32 - j0 : j0 + 1;
    int lk = (dk == 1) ? 32 - k0 : k0 + 1;
    int L  = min(li, min(lj, lk));

    const size_t base = ((size_t)((n * 2 + b) * 32 + c)) << 15;
    int idx  = i0 * 1024 + j0 * 32 + k0;
    int step = di * 1024 + dj * 32 + dk;

    float h = h0[n * 32 + c];
    for (int s = 0; s < L; s++, idx += step) {
        float zv = g_z [base + idx];
        float hv = g_hb[base + idx];
        float sv = g_s [base + idx];
        h = fmaf(zv, hv - h, h);            // z*hb + (1-z)*h
        g_hb[base + idx] = h * sv;          // contrib, in place
    }
}

// ---------------------------------------------------------------------------
// Combine: out[b,c,spatial] = sum over 8 dirs of contrib
// ---------------------------------------------------------------------------
__global__ void combine_kernel(float* __restrict__ out)
{
    int p = blockIdx.x * blockDim.x + threadIdx.x;
    if (p >= B_ * C_ * SPAT) return;
    int sp = p & (SPAT - 1);
    int t  = p >> 15;
    int c  = t & 31;
    int b  = t >> 5;
    float s = 0.f;
    #pragma unroll
    for (int n = 0; n < 8; n++)
        s += g_hb[((size_t)((n * 2 + b) * 32 + c) << 15) + sp];
    out[p] = s;
}

extern "C" void kernel_launch(void* const* d_in, const int* in_sizes, int n_in,
                              void* d_out, int out_size)
{
    const float* x  = (const float*)d_in[0];
    const float* Wh = (const float*)d_in[1];
    const float* bh = (const float*)d_in[2];
    const float* Wz = (const float*)d_in[3];
    const float* bz = (const float*)d_in[4];
    const float* Ws = (const float*)d_in[5];
    const float* bs = (const float*)d_in[6];
    const float* h0 = (const float*)d_in[7];
    float* out = (float*)d_out;

    conv_kernel<<<2048, 256>>>(x, Wh, bh, Wz, bz, Ws, bs);
    scan_kernel<<<1536, 1024>>>(h0);
    combine_kernel<<<(B_ * C_ * SPAT + 255) / 256, 256>>>(out);
}

// round 6
// speedup vs baseline: 2.6186x; 2.6147x over previous
#include <cuda_runtime.h>

// GRUConv3d: 8-direction 3D GRU with 3 conv gates per direction.
// R6: conv reformulated as implicit GEMM on mma.sync tf32 tensor cores.
//
// Pipeline:
//   prep_x / prep_w : round x and weights to tf32 (cvt.rna), repack weights
//   conv_mma_kernel : 24 convs as per-tap GEMM accumulation on tensor cores
//   scan_kernel     : diagonal GRU recurrence per dir; overwrites g_hb with O*s
//   combine_kernel  : out = sum over dirs of contrib

#define NDIR 8
#define B_   2
#define C_   32
#define SPAT 32768                      // 32*32*32
#define NT   (NDIR * B_ * C_ * SPAT)    // 16,777,216 floats per tensor

__device__ float g_hb[NT];   // conv-h output, later overwritten with contrib = O*s
__device__ float g_z [NT];   // sigmoid(conv-z)
__device__ float g_s [NT];   // sigmoid(conv-s)

__device__ float g_xt[B_ * C_ * SPAT];          // x rounded to tf32
__device__ float g_wt[24 * 27 * 32 * 32];       // W repacked [(g*27+tap)*32+ci]*32+co, tf32

__device__ __forceinline__ float to_tf32(float f) {
    unsigned u;
    asm("cvt.rna.tf32.f32 %0, %1;" : "=r"(u) : "f"(f));
    return __uint_as_float(u);
}

// ---------------------------------------------------------------------------
// Prep kernels: one-time (per launch) tf32 rounding + weight repack
// ---------------------------------------------------------------------------
__global__ void prep_x(const float* __restrict__ x)
{
    int i = blockIdx.x * 256 + threadIdx.x;
    if (i < B_ * C_ * SPAT) g_xt[i] = to_tf32(x[i]);
}

__global__ void prep_w(const float* __restrict__ Wh,
                       const float* __restrict__ Wz,
                       const float* __restrict__ Ws)
{
    int idx = blockIdx.x * 256 + threadIdx.x;
    if (idx >= 24 * 27 * 32 * 32) return;
    int co  = idx & 31;
    int ci  = (idx >> 5) & 31;
    int r   = idx >> 10;
    int tap = r % 27;
    int g   = r / 27;          // g = n*3 + gate
    int n    = g / 3;
    int gate = g % 3;
    const float* W = (gate == 0) ? Wh : (gate == 1) ? Wz : Ws;
    g_wt[idx] = to_tf32(W[(((size_t)n * 32 + co) * 32 + ci) * 27 + tap]);
}

// ---------------------------------------------------------------------------
// Implicit-GEMM conv: grid = 24 groups x 256 spatial tiles.
// Block: 256 threads (8 warps). Tile: M=32 cout, N=256 spatial (1d x 8h x 32w).
// K loop: 4 cin-chunks of 8; per chunk, 27 taps (one k8 mma-step each).
// Warp w handles h-row w of the tile: M32 x N32 = 2 m-frags x 4 n-frags.
// ---------------------------------------------------------------------------
#define MMA_TF32(d, a, b0, b1)                                               \
    asm volatile("mma.sync.aligned.m16n8k8.row.col.f32.tf32.tf32.f32 "       \
                 "{%0,%1,%2,%3}, {%4,%5,%6,%7}, {%8,%9}, {%0,%1,%2,%3};"     \
                 : "+f"(d[0]), "+f"(d[1]), "+f"(d[2]), "+f"(d[3])            \
                 : "r"(a[0]), "r"(a[1]), "r"(a[2]), "r"(a[3]),               \
                   "r"(b0), "r"(b1))

__global__ __launch_bounds__(256)
void conv_mma_kernel(const float* __restrict__ bh,
                     const float* __restrict__ bz,
                     const float* __restrict__ bs)
{
    __shared__ float Xs[8 * 1032];      // [ci8][(td*10+hh)*34+ww], stride 1032 (bank-clean)
    __shared__ float Wsm[9 * 8 * 33];   // [(tp*8+ci)*33+co], pad-33 (bank-clean)

    const int bi   = blockIdx.x;
    const int g    = bi >> 8;           // 0..23 (= n*3+gate)
    const int nt   = bi & 255;
    const int b    = nt >> 7;
    const int d    = (nt >> 2) & 31;
    const int h0v  = (nt & 3) * 8;
    const int n    = g / 3;
    const int gate = g % 3;

    const int tid  = threadIdx.x;
    const int wid  = tid >> 5;          // warp = local h row (0..7)
    const int lane = tid & 31;
    const int qrow = lane >> 2;         // 0..7
    const int qcol = lane & 3;          // 0..3

    const float* xb = g_xt + (size_t)b * (C_ * SPAT);

    float acc[2][4][4];
    #pragma unroll
    for (int f = 0; f < 2; f++)
        #pragma unroll
        for (int j = 0; j < 4; j++)
            #pragma unroll
            for (int r = 0; r < 4; r++) acc[f][j][r] = 0.f;

    for (int cc = 0; cc < 4; cc++) {            // cin chunks of 8
        __syncthreads();
        // ---- stage x chunk (zero-padded halo) ----
        for (int idx = tid; idx < 8160; idx += 256) {
            int ci = idx / 1020;
            int r  = idx % 1020;
            int ww = r % 34;
            int t  = r / 34;
            int hh = t % 10;
            int td = t / 10;
            int gd = d - 1 + td;
            int gh = h0v - 1 + hh;
            int gw = ww - 1;
            float v = 0.f;
            if ((unsigned)gd < 32u && (unsigned)gh < 32u && (unsigned)gw < 32u)
                v = xb[(size_t)(cc * 8 + ci) * SPAT + gd * 1024 + gh * 32 + gw];
            Xs[ci * 1032 + r] = v;
        }

        for (int td = 0; td < 3; td++) {
            __syncthreads();                    // prior compute done (Wsm reuse) / Xs staged
            // ---- stage weights for this (cc, td): 9 taps x 8 ci x 32 co ----
            for (int idx = tid; idx < 2304; idx += 256) {
                int co = idx & 31;
                int t  = idx >> 5;
                int ci = t & 7;
                int tp = t >> 3;                // 0..8 = th*3+tw
                Wsm[(tp * 8 + ci) * 33 + co] =
                    g_wt[((size_t)(g * 27 + td * 9 + tp) * 32 + cc * 8 + ci) * 32 + co];
            }
            __syncthreads();

            // ---- 9 taps, each one k8 mma step over the full warp tile ----
            #pragma unroll
            for (int t9 = 0; t9 < 9; t9++) {
                const int th = t9 / 3, tw = t9 % 3;
                const float* Wp = Wsm + t9 * (8 * 33);
                unsigned a[2][4];
                #pragma unroll
                for (int f = 0; f < 2; f++) {
                    int co = f * 16 + qrow;
                    a[f][0] = __float_as_uint(Wp[(qcol    ) * 33 + co    ]);
                    a[f][1] = __float_as_uint(Wp[(qcol    ) * 33 + co + 8]);
                    a[f][2] = __float_as_uint(Wp[(qcol + 4) * 33 + co    ]);
                    a[f][3] = __float_as_uint(Wp[(qcol + 4) * 33 + co + 8]);
                }
                const int xoff = (td * 10 + wid + th) * 34 + tw + qrow;
                #pragma unroll
                for (int j = 0; j < 4; j++) {
                    unsigned b0 = __float_as_uint(Xs[ qcol      * 1032 + xoff + 8 * j]);
                    unsigned b1 = __float_as_uint(Xs[(qcol + 4) * 1032 + xoff + 8 * j]);
                    MMA_TF32(acc[0][j], a[0], b0, b1);
                    MMA_TF32(acc[1][j], a[1], b0, b1);
                }
            }
        }
    }

    // ---- epilogue: bias (+ sigmoid for z,s), write scratch ----
    const float* bptr = (gate == 0) ? bh : (gate == 1) ? bz : bs;
    float* og         = (gate == 0) ? g_hb : (gate == 1) ? g_z : g_s;
    const int h = h0v + wid;
    #pragma unroll
    for (int f = 0; f < 2; f++) {
        #pragma unroll
        for (int part = 0; part < 2; part++) {
            int co = f * 16 + qrow + part * 8;
            float bias = bptr[n * 32 + co];
            float* orow = og + ((size_t)((n * 2 + b) * 32 + co)) * SPAT
                             + d * 1024 + h * 32;
            #pragma unroll
            for (int j = 0; j < 4; j++) {
                float v0 = acc[f][j][2 * part + 0] + bias;
                float v1 = acc[f][j][2 * part + 1] + bias;
                if (gate > 0) {
                    v0 = 1.f / (1.f + __expf(-v0));
                    v1 = 1.f / (1.f + __expf(-v1));
                }
                int w0 = 8 * j + 2 * qcol;
                *reinterpret_cast<float2*>(orow + w0) = make_float2(v0, v1);
            }
        }
    }
}

// ---------------------------------------------------------------------------
// Scan kernel: one thread per diagonal chain (unchanged from R5, known good).
// ---------------------------------------------------------------------------
__global__ void scan_kernel(const float* __restrict__ h0)
{
    int bid  = blockIdx.x;
    int part = bid % 3;
    int t    = bid / 3;
    int c = t & 31; t >>= 5;
    int b = t & 1;
    int n = t >> 1;

    int cid = part * 1024 + threadIdx.x;
    if (cid >= 2977) return;

    const int di = (n & 4) ? 1 : -1;
    const int dj = (n & 2) ? 1 : -1;
    const int dk = (n & 1) ? 1 : -1;
    const int si = (di == 1) ? 0 : 31;
    const int sj = (dj == 1) ? 0 : 31;
    const int sk = (dk == 1) ? 0 : 31;

    int i0, j0, k0;
    if (cid < 1024) {
        i0 = si; j0 = cid >> 5; k0 = cid & 31;
    } else if (cid < 2016) {
        int q = cid - 1024;
        j0 = sj;
        int ii = q >> 5;
        i0 = (di == 1) ? ii + 1 : ii;
        k0 = q & 31;
    } else {
        int q = cid - 2016;
        k0 = sk;
        int ii = q / 31;
        int jj = q % 31;
        i0 = (di == 1) ? ii + 1 : ii;
        j0 = (dj == 1) ? jj + 1 : jj;
    }

    int li = (di == 1) ? 32 - i0 : i0 + 1;
    int lj = (dj == 1) ? 32 - j0 : j0 + 1;
    int lk = (dk == 1) ? 32 - k0 : k0 + 1;
    int L  = min(li, min(lj, lk));

    const size_t base = ((size_t)((n * 2 + b) * 32 + c)) << 15;
    int idx  = i0 * 1024 + j0 * 32 + k0;
    int step = di * 1024 + dj * 32 + dk;

    float h = h0[n * 32 + c];
    for (int s = 0; s < L; s++, idx += step) {
        float zv = g_z [base + idx];
        float hv = g_hb[base + idx];
        float sv = g_s [base + idx];
        h = fmaf(zv, hv - h, h);            // z*hb + (1-z)*h
        g_hb[base + idx] = h * sv;          // contrib, in place
    }
}

// ---------------------------------------------------------------------------
// Combine: out[b,c,spatial] = sum over 8 dirs of contrib
// ---------------------------------------------------------------------------
__global__ void combine_kernel(float* __restrict__ out)
{
    int p = blockIdx.x * blockDim.x + threadIdx.x;
    if (p >= B_ * C_ * SPAT) return;
    int sp = p & (SPAT - 1);
    int t  = p >> 15;
    int c  = t & 31;
    int b  = t >> 5;
    float s = 0.f;
    #pragma unroll
    for (int n = 0; n < 8; n++)
        s += g_hb[((size_t)((n * 2 + b) * 32 + c) << 15) + sp];
    out[p] = s;
}

extern "C" void kernel_launch(void* const* d_in, const int* in_sizes, int n_in,
                              void* d_out, int out_size)
{
    const float* x  = (const float*)d_in[0];
    const float* Wh = (const float*)d_in[1];
    const float* bh = (const float*)d_in[2];
    const float* Wz = (const float*)d_in[3];
    const float* bz = (const float*)d_in[4];
    const float* Ws = (const float*)d_in[5];
    const float* bs = (const float*)d_in[6];
    const float* h0 = (const float*)d_in[7];
    float* out = (float*)d_out;

    prep_x<<<(B_ * C_ * SPAT + 255) / 256, 256>>>(x);
    prep_w<<<(24 * 27 * 32 * 32 + 255) / 256, 256>>>(Wh, Wz, Ws);
    conv_mma_kernel<<<24 * 256, 256>>>(bh, bz, bs);
    scan_kernel<<<1536, 1024>>>(h0);
    combine_kernel<<<(B_ * C_ * SPAT + 255) / 256, 256>>>(out);
}

// round 9
// speedup vs baseline: 3.6908x; 1.4095x over previous
#include <cuda_runtime.h>
#include <cstdint>

// GRUConv3d R9: legacy mma.sync tf32 conv, 2 gate-groups per block (x reuse,
// shared B-fragments), lane-ordered A-fragments (LDS.128). tcgen05 is not
// available at this toolchain's PTX target (sm_103 family), per R8.

#define NDIR 8
#define B_   2
#define C_   32
#define SPAT 32768
#define NT   (NDIR * B_ * C_ * SPAT)

__device__ float g_hb[NT];   // conv-h out, later overwritten with contrib = O*s
__device__ float g_z [NT];
__device__ float g_s [NT];
__device__ __align__(16) float g_xt[B_ * C_ * SPAT];        // x rounded to tf32
// weight fragments: [g 24][cc 4][td 3][t9 9][f 2][lane 32][r 4]
__device__ __align__(16) float g_wt[24 * 4 * 3 * 9 * 256];

__device__ __forceinline__ float to_tf32(float f) {
    unsigned u; asm("cvt.rna.tf32.f32 %0, %1;" : "=r"(u) : "f"(f));
    return __uint_as_float(u);
}

// ---------------------------------------------------------------------------
// Prep: round x to tf32; emit lane-ordered tf32 A-fragments for the weights.
// m16n8k8 A-frag (row=cout, col=k): a0=A[qrow][qcol], a1=A[qrow+8][qcol],
// a2=A[qrow][qcol+4], a3=A[qrow+8][qcol+4], qrow=lane>>2, qcol=lane&3.
// ---------------------------------------------------------------------------
__global__ void prep_x(const float* __restrict__ x)
{
    int i = blockIdx.x * 256 + threadIdx.x;
    if (i < B_ * C_ * SPAT) g_xt[i] = to_tf32(x[i]);
}

__global__ void prep_w(const float* __restrict__ Wh,
                       const float* __restrict__ Wz,
                       const float* __restrict__ Ws)
{
    int idx = blockIdx.x * 256 + threadIdx.x;
    if (idx >= 24 * 4 * 3 * 9 * 256) return;
    int r    = idx & 3;
    int lane = (idx >> 2) & 31;
    int f    = (idx >> 7) & 1;
    int t9   = (idx >> 8) % 9;
    int q    = (idx >> 8) / 9;
    int td = q % 3; q /= 3;
    int cc = q & 3; int g = q >> 2;

    int qrow = lane >> 2, qcol = lane & 3;
    int co = f * 16 + qrow + (r & 1) * 8;
    int k  = qcol + (r >> 1) * 4;
    int th = t9 / 3, tw = t9 % 3;
    int ci = cc * 8 + k;
    int n = g / 3, gate = g % 3;
    const float* W = (gate == 0) ? Wh : (gate == 1) ? Wz : Ws;
    g_wt[idx] = to_tf32(W[(((size_t)n * 32 + co) * 32 + ci) * 27 + td * 9 + th * 3 + tw]);
}

// ---------------------------------------------------------------------------
// Conv: grid = 12 group-pairs x 256 tiles (b, d, h-quarter). Block 256 thr.
// Per block: M=32 cout x 2 groups, N=256 spatial (1d x 8h x 32w), K=864.
// Warp = h row. acc[group][f][j][4]. Xs staged once per cc chunk, shared by
// both groups; B-fragments loaded once per (tap,j) and reused by 4 MMAs.
// ---------------------------------------------------------------------------
#define MMA_TF32(d, a, b0, b1)                                               \
    asm volatile("mma.sync.aligned.m16n8k8.row.col.f32.tf32.tf32.f32 "       \
                 "{%0,%1,%2,%3}, {%4,%5,%6,%7}, {%8,%9}, {%0,%1,%2,%3};"     \
                 : "+f"(d[0]), "+f"(d[1]), "+f"(d[2]), "+f"(d[3])            \
                 : "r"(a.x), "r"(a.y), "r"(a.z), "r"(a.w),                   \
                   "r"(b0), "r"(b1))

#define XS_STRIDE 1032
#define WF_OFF    8256                 // 8*1032 floats
#define SM_FLOATS (WF_OFF + 4608)      // + 2*9*2*128
#define SM_BYTES  (SM_FLOATS * 4)      // 51456 B

extern "C" __global__ void __launch_bounds__(256, 2)
conv_mma2(const float* __restrict__ bh, const float* __restrict__ bz,
          const float* __restrict__ bs)
{
    extern __shared__ float sm[];
    float* Xs = sm;                    // [ci8][(td*10+hh)*34+ww], stride 1032
    float* WF = sm + WF_OFF;           // [g2][t9][f][lane][4]

    const int ng  = blockIdx.x >> 8;   // 0..11
    const int nt  = blockIdx.x & 255;
    const int b   = nt >> 7;
    const int d   = (nt >> 2) & 31;
    const int h0v = (nt & 3) * 8;
    const int g0  = ng * 2;

    const int tid  = threadIdx.x;
    const int wid  = tid >> 5;
    const int lane = tid & 31;
    const int qrow = lane >> 2;
    const int qcol = lane & 3;

    const float* xb = g_xt + (size_t)b * (C_ * SPAT);

    float acc[2][2][4][4];
    #pragma unroll
    for (int gi = 0; gi < 2; gi++)
        #pragma unroll
        for (int f = 0; f < 2; f++)
            #pragma unroll
            for (int j = 0; j < 4; j++)
                #pragma unroll
                for (int r = 0; r < 4; r++) acc[gi][f][j][r] = 0.f;

    for (int cc = 0; cc < 4; cc++) {
        __syncthreads();                       // prev compute done with Xs
        // ---- stage x chunk (zero-padded halo) ----
        for (int idx = tid; idx < 8160; idx += 256) {
            int ci = idx / 1020;
            int r  = idx % 1020;
            int ww = r % 34;
            int t  = r / 34;
            int hh = t % 10;
            int td = t / 10;
            int gd = d - 1 + td;
            int gh = h0v - 1 + hh;
            int gw = ww - 1;
            float v = 0.f;
            if ((unsigned)gd < 32u && (unsigned)gh < 32u && (unsigned)gw < 32u)
                v = xb[(size_t)(cc * 8 + ci) * SPAT + gd * 1024 + gh * 32 + gw];
            Xs[ci * XS_STRIDE + r] = v;
        }

        for (int td = 0; td < 3; td++) {
            __syncthreads();                   // prev compute done with WF
            // ---- stage weight frags for both groups: 2 x 2304 floats ----
            {
                const float4* w0 = (const float4*)(g_wt +
                    ((size_t)((g0    ) * 4 + cc) * 3 + td) * (9 * 256));
                const float4* w1 = (const float4*)(g_wt +
                    ((size_t)((g0 + 1) * 4 + cc) * 3 + td) * (9 * 256));
                float4* wf0 = (float4*)WF;
                float4* wf1 = (float4*)(WF + 2304);
                for (int i4 = tid; i4 < 576; i4 += 256) {
                    wf0[i4] = w0[i4];
                    wf1[i4] = w1[i4];
                }
            }
            __syncthreads();

            // ---- 9 taps; per tap: 4 LDS.128 (A) + 8 LDS.32 (B) + 16 MMA ----
            #pragma unroll
            for (int t9 = 0; t9 < 9; t9++) {
                const int th = t9 / 3, tw = t9 % 3;
                const uint4 a00 = *(const uint4*)(WF +        (t9 * 2    ) * 128 + lane * 4);
                const uint4 a01 = *(const uint4*)(WF +        (t9 * 2 + 1) * 128 + lane * 4);
                const uint4 a10 = *(const uint4*)(WF + 2304 + (t9 * 2    ) * 128 + lane * 4);
                const uint4 a11 = *(const uint4*)(WF + 2304 + (t9 * 2 + 1) * 128 + lane * 4);
                const int xoff = (td * 10 + wid + th) * 34 + tw + qrow;
                #pragma unroll
                for (int j = 0; j < 4; j++) {
                    unsigned b0 = __float_as_uint(Xs[ qcol      * XS_STRIDE + xoff + 8 * j]);
                    unsigned b1 = __float_as_uint(Xs[(qcol + 4) * XS_STRIDE + xoff + 8 * j]);
                    MMA_TF32(acc[0][0][j], a00, b0, b1);
                    MMA_TF32(acc[0][1][j], a01, b0, b1);
                    MMA_TF32(acc[1][0][j], a10, b0, b1);
                    MMA_TF32(acc[1][1][j], a11, b0, b1);
                }
            }
        }
    }

    // ---- epilogue: bias (+ sigmoid for z,s), write scratch ----
    const int h = h0v + wid;
    #pragma unroll
    for (int gi = 0; gi < 2; gi++) {
        const int g = g0 + gi, gate = g % 3, n = g / 3;
        const float* bptr = (gate == 0) ? bh : (gate == 1) ? bz : bs;
        float* og         = (gate == 0) ? g_hb : (gate == 1) ? g_z : g_s;
        #pragma unroll
        for (int f = 0; f < 2; f++) {
            #pragma unroll
            for (int part = 0; part < 2; part++) {
                int co = f * 16 + qrow + part * 8;
                float bias = bptr[n * 32 + co];
                float* orow = og + ((size_t)((n * 2 + b) * 32 + co)) * SPAT
                                 + d * 1024 + h * 32;
                #pragma unroll
                for (int j = 0; j < 4; j++) {
                    float v0 = acc[gi][f][j][2 * part + 0] + bias;
                    float v1 = acc[gi][f][j][2 * part + 1] + bias;
                    if (gate > 0) {
                        v0 = 1.f / (1.f + __expf(-v0));
                        v1 = 1.f / (1.f + __expf(-v1));
                    }
                    int w0 = 8 * j + 2 * qcol;
                    *reinterpret_cast<float2*>(orow + w0) = make_float2(v0, v1);
                }
            }
        }
    }
}

// ---------------------------------------------------------------------------
// Scan: one thread per diagonal chain, 1-deep software prefetch.
// ---------------------------------------------------------------------------
__global__ void scan_kernel(const float* __restrict__ h0)
{
    int bid  = blockIdx.x;
    int part = bid % 3;
    int t    = bid / 3;
    int c = t & 31; t >>= 5;
    int b = t & 1;
    int n = t >> 1;

    int cid = part * 1024 + threadIdx.x;
    if (cid >= 2977) return;

    const int di = (n & 4) ? 1 : -1;
    const int dj = (n & 2) ? 1 : -1;
    const int dk = (n & 1) ? 1 : -1;
    const int si = (di == 1) ? 0 : 31;
    const int sj = (dj == 1) ? 0 : 31;
    const int sk = (dk == 1) ? 0 : 31;

    int i0, j0, k0;
    if (cid < 1024) {
        i0 = si; j0 = cid >> 5; k0 = cid & 31;
    } else if (cid < 2016) {
        int q = cid - 1024;
        j0 = sj;
        int ii = q >> 5;
        i0 = (di == 1) ? ii + 1 : ii;
        k0 = q & 31;
    } else {
        int q = cid - 2016;
        k0 = sk;
        int ii = q / 31;
        int jj = q % 31;
        i0 = (di == 1) ? ii + 1 : ii;
        j0 = (dj == 1) ? jj + 1 : jj;
    }

    int li = (di == 1) ? 32 - i0 : i0 + 1;
    int lj = (dj == 1) ? 32 - j0 : j0 + 1;
    int lk = (dk == 1) ? 32 - k0 : k0 + 1;
    int L  = min(li, min(lj, lk));

    const long long base = ((long long)((n * 2 + b) * 32 + c)) << 15;
    const int step = di * 1024 + dj * 32 + dk;
    long long p = base + i0 * 1024 + j0 * 32 + k0;

    float h = h0[n * 32 + c];
    float zv = g_z[p], hv = g_hb[p], sv = g_s[p];
    for (int s = 0; s < L; s++) {
        long long pn = p + step;
        float zn = 0.f, hn = 0.f, sn = 0.f;
        if (s + 1 < L) { zn = g_z[pn]; hn = g_hb[pn]; sn = g_s[pn]; }
        h = fmaf(zv, hv - h, h);            // z*hb + (1-z)*h
        g_hb[p] = h * sv;                   // contrib, in place
        zv = zn; hv = hn; sv = sn; p = pn;
    }
}

// ---------------------------------------------------------------------------
// Combine: out[b,c,spatial] = sum over 8 dirs of contrib
// ---------------------------------------------------------------------------
__global__ void combine_kernel(float* __restrict__ out)
{
    int p = blockIdx.x * blockDim.x + threadIdx.x;
    if (p >= B_ * C_ * SPAT) return;
    int sp = p & (SPAT - 1);
    int t  = p >> 15;
    int c  = t & 31;
    int b  = t >> 5;
    float s = 0.f;
    #pragma unroll
    for (int n = 0; n < 8; n++)
        s += g_hb[((size_t)((n * 2 + b) * 32 + c) << 15) + sp];
    out[p] = s;
}

extern "C" void kernel_launch(void* const* d_in, const int* in_sizes, int n_in,
                              void* d_out, int out_size)
{
    const float* x  = (const float*)d_in[0];
    const float* Wh = (const float*)d_in[1];
    const float* bh = (const float*)d_in[2];
    const float* Wz = (const float*)d_in[3];
    const float* bz = (const float*)d_in[4];
    const float* Ws = (const float*)d_in[5];
    const float* bs = (const float*)d_in[6];
    const float* h0 = (const float*)d_in[7];
    float* out = (float*)d_out;

    cudaFuncSetAttribute(conv_mma2, cudaFuncAttributeMaxDynamicSharedMemorySize, SM_BYTES);

    prep_x<<<(B_ * C_ * SPAT + 255) / 256, 256>>>(x);
    prep_w<<<(24 * 4 * 3 * 9 * 256 + 255) / 256, 256>>>(Wh, Wz, Ws);
    conv_mma2<<<12 * 256, 256, SM_BYTES>>>(bh, bz, bs);
    scan_kernel<<<1536, 1024>>>(h0);
    combine_kernel<<<(B_ * C_ * SPAT + 255) / 256, 256>>>(out);
}

// round 12
// speedup vs baseline: 5.7414x; 1.5556x over previous
#include <cuda_runtime.h>
#include <cuda_fp16.h>
#include <cstdint>

// GRUConv3d R11: conv on legacy mma.sync m16n8k16 fp16 (fp32 accumulate).
// fp16 mantissa (2^-11) == tf32 rounding, but 2x FLOP per MMA instruction.
// Structure from R9: 2 gate-groups per block, lane-ordered A-frags (LDS.128),
// x staged as half2 packing two consecutive cin per word (B-frag native).
// R11 = R10 with the __half2_as_uint portability fix (pack via __half_as_ushort).

#define NDIR 8
#define B_   2
#define C_   32
#define SPAT 32768
#define NT   (NDIR * B_ * C_ * SPAT)

__device__ float g_hb[NT];   // conv-h out, later overwritten with contrib = O*s
__device__ float g_z [NT];
__device__ float g_s [NT];
__device__ __align__(16) __half g_xh[B_ * C_ * SPAT];       // x rounded to fp16
// weight frags: [g 24][cc2 2][td 3][t9 9][f 2][lane 32][r 4] (half2 words)
__device__ __align__(16) unsigned g_wt[24 * 2 * 3 * 9 * 256];

// pack two halves into one 32-bit word: lo in bits [0:16), hi in [16:32)
__device__ __forceinline__ unsigned pack_h2(__half lo, __half hi) {
    return (unsigned)__half_as_ushort(lo) | ((unsigned)__half_as_ushort(hi) << 16);
}

// ---------------------------------------------------------------------------
// Prep kernels
// ---------------------------------------------------------------------------
__global__ void prep_x(const float* __restrict__ x)
{
    int i = blockIdx.x * 256 + threadIdx.x;
    if (i < B_ * C_ * SPAT) g_xh[i] = __float2half_rn(x[i]);
}

// m16n8k16 A-frag (row=cout, col=k): lane(qrow=lane>>2,qcol=lane&3)
//  a0={A[qrow][2qcol],A[qrow][2qcol+1]}  a1={A[qrow+8][same k]}
//  a2={A[qrow][2qcol+8],A[qrow][2qcol+9]} a3={A[qrow+8][k hi]}
// uint4 regs: x=a0, y=a1, z=a2, w=a3 -> r&1 selects +8 row, r>>1 selects k+8.
__global__ void prep_w(const float* __restrict__ Wh,
                       const float* __restrict__ Wz,
                       const float* __restrict__ Ws)
{
    int idx = blockIdx.x * 256 + threadIdx.x;
    if (idx >= 24 * 2 * 3 * 9 * 256) return;
    int r    = idx & 3;
    int lane = (idx >> 2) & 31;
    int f    = (idx >> 7) & 1;
    int t9   = (idx >> 8) % 9;
    int q    = (idx >> 8) / 9;
    int td  = q % 3; q /= 3;
    int cc2 = q & 1; int g = q >> 1;

    int qrow = lane >> 2, qcol = lane & 3;
    int co = f * 16 + qrow + (r & 1) * 8;
    int k0 = 2 * qcol + (r >> 1) * 8;
    int th = t9 / 3, tw = t9 % 3;
    int ci0 = cc2 * 16 + k0;
    int n = g / 3, gate = g % 3;
    const float* W = (gate == 0) ? Wh : (gate == 1) ? Wz : Ws;
    size_t wb = ((size_t)n * 32 + co) * 32;
    int tap = td * 9 + th * 3 + tw;
    __half lo = __float2half_rn(W[(wb + ci0    ) * 27 + tap]);
    __half hi = __float2half_rn(W[(wb + ci0 + 1) * 27 + tap]);
    g_wt[idx] = pack_h2(lo, hi);
}

// ---------------------------------------------------------------------------
// Conv: grid = 12 group-pairs x 256 tiles (b, d, h-quarter). Block 256 thr.
// Per block: M=32 cout x 2 groups, N=256 spatial (1d x 8h x 32w), K=864.
// K loop: 2 cin-chunks of 16; per chunk 27 taps (one k16 mma-step each).
// Xs holds half2 words pairing cin (2cp, 2cp+1): B-frag loads are LDS.32.
// ---------------------------------------------------------------------------
#define MMA_F16(d, a, b0, b1)                                                \
    asm volatile("mma.sync.aligned.m16n8k16.row.col.f32.f16.f16.f32 "        \
                 "{%0,%1,%2,%3}, {%4,%5,%6,%7}, {%8,%9}, {%0,%1,%2,%3};"     \
                 : "+f"(d[0]), "+f"(d[1]), "+f"(d[2]), "+f"(d[3])            \
                 : "r"(a.x), "r"(a.y), "r"(a.z), "r"(a.w),                   \
                   "r"(b0), "r"(b1))

#define XS_STRIDE 1032                 // half2 words; %32 == 8 -> bank-clean
#define WF_OFF    8256                 // 8*1032 words
#define SM_WORDS  (WF_OFF + 4608)      // + 2*(9*2*128)
#define SM_BYTES  (SM_WORDS * 4)       // 51456 B

extern "C" __global__ void __launch_bounds__(256, 2)
conv_mma2(const float* __restrict__ bh, const float* __restrict__ bz,
          const float* __restrict__ bs)
{
    extern __shared__ unsigned sm[];
    unsigned* Xs = sm;                 // [cp 8][(td*10+hh)*34+ww] half2 words
    unsigned* WF = sm + WF_OFF;        // [g2][t9][f][lane][4]

    const int ng  = blockIdx.x >> 8;   // 0..11
    const int nt  = blockIdx.x & 255;
    const int b   = nt >> 7;
    const int d   = (nt >> 2) & 31;
    const int h0v = (nt & 3) * 8;
    const int g0  = ng * 2;

    const int tid  = threadIdx.x;
    const int wid  = tid >> 5;
    const int lane = tid & 31;
    const int qrow = lane >> 2;
    const int qcol = lane & 3;

    const __half* xb = g_xh + (size_t)b * (C_ * SPAT);

    float acc[2][2][4][4];
    #pragma unroll
    for (int gi = 0; gi < 2; gi++)
        #pragma unroll
        for (int f = 0; f < 2; f++)
            #pragma unroll
            for (int j = 0; j < 4; j++)
                #pragma unroll
                for (int r = 0; r < 4; r++) acc[gi][f][j][r] = 0.f;

    for (int cc2 = 0; cc2 < 2; cc2++) {        // cin chunks of 16
        __syncthreads();                       // prev compute done with Xs
        // ---- stage x chunk: pack cin pair (2cp,2cp+1) into half2 words ----
        for (int idx = tid; idx < 8160; idx += 256) {
            int cp = idx / 1020;
            int r  = idx % 1020;
            int ww = r % 34;
            int t  = r / 34;
            int hh = t % 10;
            int td = t / 10;
            int gd = d - 1 + td;
            int gh = h0v - 1 + hh;
            int gw = ww - 1;
            unsigned v = 0u;
            if ((unsigned)gd < 32u && (unsigned)gh < 32u && (unsigned)gw < 32u) {
                size_t off = (size_t)(cc2 * 16 + cp * 2) * SPAT
                           + gd * 1024 + gh * 32 + gw;
                v = pack_h2(xb[off], xb[off + SPAT]);
            }
            Xs[cp * XS_STRIDE + r] = v;
        }

        for (int td = 0; td < 3; td++) {
            __syncthreads();                   // prev compute done with WF
            // ---- stage weight frags for both groups: 2 x 2304 words ----
            {
                const uint4* w0 = (const uint4*)(g_wt +
                    ((size_t)((g0    ) * 2 + cc2) * 3 + td) * 2304);
                const uint4* w1 = (const uint4*)(g_wt +
                    ((size_t)((g0 + 1) * 2 + cc2) * 3 + td) * 2304);
                uint4* wf0 = (uint4*)WF;
                uint4* wf1 = (uint4*)(WF + 2304);
                for (int i4 = tid; i4 < 576; i4 += 256) {
                    wf0[i4] = w0[i4];
                    wf1[i4] = w1[i4];
                }
            }
            __syncthreads();

            // ---- 9 taps; per tap: 4 LDS.128 (A) + 8 LDS.32 (B) + 16 MMA ----
            #pragma unroll
            for (int t9 = 0; t9 < 9; t9++) {
                const int th = t9 / 3, tw = t9 % 3;
                const uint4 a00 = *(const uint4*)(WF +        (t9 * 2    ) * 128 + lane * 4);
                const uint4 a01 = *(const uint4*)(WF +        (t9 * 2 + 1) * 128 + lane * 4);
                const uint4 a10 = *(const uint4*)(WF + 2304 + (t9 * 2    ) * 128 + lane * 4);
                const uint4 a11 = *(const uint4*)(WF + 2304 + (t9 * 2 + 1) * 128 + lane * 4);
                const int xoff = (td * 10 + wid + th) * 34 + tw + qrow;
                #pragma unroll
                for (int j = 0; j < 4; j++) {
                    unsigned b0 = Xs[ qcol      * XS_STRIDE + xoff + 8 * j];
                    unsigned b1 = Xs[(qcol + 4) * XS_STRIDE + xoff + 8 * j];
                    MMA_F16(acc[0][0][j], a00, b0, b1);
                    MMA_F16(acc[0][1][j], a01, b0, b1);
                    MMA_F16(acc[1][0][j], a10, b0, b1);
                    MMA_F16(acc[1][1][j], a11, b0, b1);
                }
            }
        }
    }

    // ---- epilogue: bias (+ sigmoid for z,s), write scratch ----
    const int h = h0v + wid;
    #pragma unroll
    for (int gi = 0; gi < 2; gi++) {
        const int g = g0 + gi, gate = g % 3, n = g / 3;
        const float* bptr = (gate == 0) ? bh : (gate == 1) ? bz : bs;
        float* og         = (gate == 0) ? g_hb : (gate == 1) ? g_z : g_s;
        #pragma unroll
        for (int f = 0; f < 2; f++) {
            #pragma unroll
            for (int part = 0; part < 2; part++) {
                int co = f * 16 + qrow + part * 8;
                float bias = bptr[n * 32 + co];
                float* orow = og + ((size_t)((n * 2 + b) * 32 + co)) * SPAT
                                 + d * 1024 + h * 32;
                #pragma unroll
                for (int j = 0; j < 4; j++) {
                    float v0 = acc[gi][f][j][2 * part + 0] + bias;
                    float v1 = acc[gi][f][j][2 * part + 1] + bias;
                    if (gate > 0) {
                        v0 = 1.f / (1.f + __expf(-v0));
                        v1 = 1.f / (1.f + __expf(-v1));
                    }
                    int w0 = 8 * j + 2 * qcol;
                    *reinterpret_cast<float2*>(orow + w0) = make_float2(v0, v1);
                }
            }
        }
    }
}

// ---------------------------------------------------------------------------
// Scan: one thread per diagonal chain, 1-deep software prefetch (R9, good).
// ---------------------------------------------------------------------------
__global__ void scan_kernel(const float* __restrict__ h0)
{
    int bid  = blockIdx.x;
    int part = bid % 3;
    int t    = bid / 3;
    int c = t & 31; t >>= 5;
    int b = t & 1;
    int n = t >> 1;

    int cid = part * 1024 + threadIdx.x;
    if (cid >= 2977) return;

    const int di = (n & 4) ? 1 : -1;
    const int dj = (n & 2) ? 1 : -1;
    const int dk = (n & 1) ? 1 : -1;
    const int si = (di == 1) ? 0 : 31;
    const int sj = (dj == 1) ? 0 : 31;
    const int sk = (dk == 1) ? 0 : 31;

    int i0, j0, k0;
    if (cid < 1024) {
        i0 = si; j0 = cid >> 5; k0 = cid & 31;
    } else if (cid < 2016) {
        int q = cid - 1024;
        j0 = sj;
        int ii = q >> 5;
        i0 = (di == 1) ? ii + 1 : ii;
        k0 = q & 31;
    } else {
        int q = cid - 2016;
        k0 = sk;
        int ii = q / 31;
        int jj = q % 31;
        i0 = (di == 1) ? ii + 1 : ii;
        j0 = (dj == 1) ? jj + 1 : jj;
    }

    int li = (di == 1) ? 32 - i0 : i0 + 1;
    int lj = (dj == 1) ? 32 - j0 : j0 + 1;
    int lk = (dk == 1) ? 32 - k0 : k0 + 1;
    int L  = min(li, min(lj, lk));

    const long long base = ((long long)((n * 2 + b) * 32 + c)) << 15;
    const int step = di * 1024 + dj * 32 + dk;
    long long p = base + i0 * 1024 + j0 * 32 + k0;

    float h = h0[n * 32 + c];
    float zv = g_z[p], hv = g_hb[p], sv = g_s[p];
    for (int s = 0; s < L; s++) {
        long long pn = p + step;
        float zn = 0.f, hn = 0.f, sn = 0.f;
        if (s + 1 < L) { zn = g_z[pn]; hn = g_hb[pn]; sn = g_s[pn]; }
        h = fmaf(zv, hv - h, h);            // z*hb + (1-z)*h
        g_hb[p] = h * sv;                   // contrib, in place
        zv = zn; hv = hn; sv = sn; p = pn;
    }
}

// ---------------------------------------------------------------------------
// Combine: out[b,c,spatial] = sum over 8 dirs of contrib
// ---------------------------------------------------------------------------
__global__ void combine_kernel(float* __restrict__ out)
{
    int p = blockIdx.x * blockDim.x + threadIdx.x;
    if (p >= B_ * C_ * SPAT) return;
    int sp = p & (SPAT - 1);
    int t  = p >> 15;
    int c  = t & 31;
    int b  = t >> 5;
    float s = 0.f;
    #pragma unroll
    for (int n = 0; n < 8; n++)
        s += g_hb[((size_t)((n * 2 + b) * 32 + c) << 15) + sp];
    out[p] = s;
}

extern "C" void kernel_launch(void* const* d_in, const int* in_sizes, int n_in,
                              void* d_out, int out_size)
{
    const float* x  = (const float*)d_in[0];
    const float* Wh = (const float*)d_in[1];
    const float* bh = (const float*)d_in[2];
    const float* Wz = (const float*)d_in[3];
    const float* bz = (const float*)d_in[4];
    const float* Ws = (const float*)d_in[5];
    const float* bs = (const float*)d_in[6];
    const float* h0 = (const float*)d_in[7];
    float* out = (float*)d_out;

    cudaFuncSetAttribute(conv_mma2, cudaFuncAttributeMaxDynamicSharedMemorySize, SM_BYTES);

    prep_x<<<(B_ * C_ * SPAT + 255) / 256, 256>>>(x);
    prep_w<<<(24 * 2 * 3 * 9 * 256 + 255) / 256, 256>>>(Wh, Wz, Ws);
    conv_mma2<<<12 * 256, 256, SM_BYTES>>>(bh, bz, bs);
    scan_kernel<<<1536, 1024>>>(h0);
    combine_kernel<<<(B_ * C_ * SPAT + 255) / 256, 256>>>(out);
}

// round 16
// speedup vs baseline: 6.5791x; 1.1459x over previous
#include <cuda_runtime.h>
#include <cuda_fp16.h>
#include <cstdint>

// GRUConv3d R16 (= R15 resubmit after infra failure; R14 + combine fix):
// channel-last scratch layout [n,b,sp,c]. Scan: one WARP per diagonal chain,
// lane = channel -> zero divergence, fully coalesced 128B lines.
// Conv epilogue + combine do smem transposes. Conv mainloop = R11
// (mma.sync m16n8k16 fp16, fp32 accumulate).

#define NDIR 8
#define B_   2
#define C_   32
#define SPAT 32768
#define NT   (NDIR * B_ * C_ * SPAT)

// scratch tensors, layout [n][b][sp][c]  (c fastest)
__device__ float g_hb[NT];   // conv-h out, later overwritten with contrib = O*s
__device__ float g_z [NT];
__device__ float g_s [NT];
__device__ __align__(16) __half g_xh[B_ * C_ * SPAT];       // x rounded to fp16
// weight frags: [g 24][cc2 2][td 3][t9 9][f 2][lane 32][r 4] (half2 words)
__device__ __align__(16) unsigned g_wt[24 * 2 * 3 * 9 * 256];

__device__ __forceinline__ unsigned pack_h2(__half lo, __half hi) {
    return (unsigned)__half_as_ushort(lo) | ((unsigned)__half_as_ushort(hi) << 16);
}

// ---------------------------------------------------------------------------
// Prep kernels
// ---------------------------------------------------------------------------
__global__ void prep_x(const float* __restrict__ x)
{
    int i = blockIdx.x * 256 + threadIdx.x;
    if (i < B_ * C_ * SPAT) g_xh[i] = __float2half_rn(x[i]);
}

__global__ void prep_w(const float* __restrict__ Wh,
                       const float* __restrict__ Wz,
                       const float* __restrict__ Ws)
{
    int idx = blockIdx.x * 256 + threadIdx.x;
    if (idx >= 24 * 2 * 3 * 9 * 256) return;
    int r    = idx & 3;
    int lane = (idx >> 2) & 31;
    int f    = (idx >> 7) & 1;
    int t9   = (idx >> 8) % 9;
    int q    = (idx >> 8) / 9;
    int td  = q % 3; q /= 3;
    int cc2 = q & 1; int g = q >> 1;

    int qrow = lane >> 2, qcol = lane & 3;
    int co = f * 16 + qrow + (r & 1) * 8;
    int k0 = 2 * qcol + (r >> 1) * 8;
    int th = t9 / 3, tw = t9 % 3;
    int ci0 = cc2 * 16 + k0;
    int n = g / 3, gate = g % 3;
    const float* W = (gate == 0) ? Wh : (gate == 1) ? Wz : Ws;
    size_t wb = ((size_t)n * 32 + co) * 32;
    int tap = td * 9 + th * 3 + tw;
    __half lo = __float2half_rn(W[(wb + ci0    ) * 27 + tap]);
    __half hi = __float2half_rn(W[(wb + ci0 + 1) * 27 + tap]);
    g_wt[idx] = pack_h2(lo, hi);
}

// ---------------------------------------------------------------------------
// Conv (mainloop identical to R11); epilogue transposes to [sp][c] via smem.
// ---------------------------------------------------------------------------
#define MMA_F16(d, a, b0, b1)                                                \
    asm volatile("mma.sync.aligned.m16n8k16.row.col.f32.f16.f16.f32 "        \
                 "{%0,%1,%2,%3}, {%4,%5,%6,%7}, {%8,%9}, {%0,%1,%2,%3};"     \
                 : "+f"(d[0]), "+f"(d[1]), "+f"(d[2]), "+f"(d[3])            \
                 : "r"(a.x), "r"(a.y), "r"(a.z), "r"(a.w),                   \
                   "r"(b0), "r"(b1))

#define XS_STRIDE 1032
#define WF_OFF    8256
#define SM_WORDS  (WF_OFF + 4608)
#define SM_BYTES  (SM_WORDS * 4)       // 51456 B (>= 256*36*4 = 36864 for Ts)

extern "C" __global__ void __launch_bounds__(256, 2)
conv_mma2(const float* __restrict__ bh, const float* __restrict__ bz,
          const float* __restrict__ bs)
{
    extern __shared__ unsigned sm[];
    unsigned* Xs = sm;                 // [cp 8][(td*10+hh)*34+ww] half2 words
    unsigned* WF = sm + WF_OFF;        // [g2][t9][f][lane][4]

    const int ng  = blockIdx.x >> 8;   // 0..11
    const int nt  = blockIdx.x & 255;
    const int b   = nt >> 7;
    const int d   = (nt >> 2) & 31;
    const int h0v = (nt & 3) * 8;
    const int g0  = ng * 2;

    const int tid  = threadIdx.x;
    const int wid  = tid >> 5;
    const int lane = tid & 31;
    const int qrow = lane >> 2;
    const int qcol = lane & 3;

    const __half* xb = g_xh + (size_t)b * (C_ * SPAT);

    float acc[2][2][4][4];
    #pragma unroll
    for (int gi = 0; gi < 2; gi++)
        #pragma unroll
        for (int f = 0; f < 2; f++)
            #pragma unroll
            for (int j = 0; j < 4; j++)
                #pragma unroll
                for (int r = 0; r < 4; r++) acc[gi][f][j][r] = 0.f;

    for (int cc2 = 0; cc2 < 2; cc2++) {        // cin chunks of 16
        __syncthreads();
        for (int idx = tid; idx < 8160; idx += 256) {
            int cp = idx / 1020;
            int r  = idx % 1020;
            int ww = r % 34;
            int t  = r / 34;
            int hh = t % 10;
            int td = t / 10;
            int gd = d - 1 + td;
            int gh = h0v - 1 + hh;
            int gw = ww - 1;
            unsigned v = 0u;
            if ((unsigned)gd < 32u && (unsigned)gh < 32u && (unsigned)gw < 32u) {
                size_t off = (size_t)(cc2 * 16 + cp * 2) * SPAT
                           + gd * 1024 + gh * 32 + gw;
                v = pack_h2(xb[off], xb[off + SPAT]);
            }
            Xs[cp * XS_STRIDE + r] = v;
        }

        for (int td = 0; td < 3; td++) {
            __syncthreads();
            {
                const uint4* w0 = (const uint4*)(g_wt +
                    ((size_t)((g0    ) * 2 + cc2) * 3 + td) * 2304);
                const uint4* w1 = (const uint4*)(g_wt +
                    ((size_t)((g0 + 1) * 2 + cc2) * 3 + td) * 2304);
                uint4* wf0 = (uint4*)WF;
                uint4* wf1 = (uint4*)(WF + 2304);
                for (int i4 = tid; i4 < 576; i4 += 256) {
                    wf0[i4] = w0[i4];
                    wf1[i4] = w1[i4];
                }
            }
            __syncthreads();

            #pragma unroll
            for (int t9 = 0; t9 < 9; t9++) {
                const int th = t9 / 3, tw = t9 % 3;
                const uint4 a00 = *(const uint4*)(WF +        (t9 * 2    ) * 128 + lane * 4);
                const uint4 a01 = *(const uint4*)(WF +        (t9 * 2 + 1) * 128 + lane * 4);
                const uint4 a10 = *(const uint4*)(WF + 2304 + (t9 * 2    ) * 128 + lane * 4);
                const uint4 a11 = *(const uint4*)(WF + 2304 + (t9 * 2 + 1) * 128 + lane * 4);
                const int xoff = (td * 10 + wid + th) * 34 + tw + qrow;
                #pragma unroll
                for (int j = 0; j < 4; j++) {
                    unsigned b0 = Xs[ qcol      * XS_STRIDE + xoff + 8 * j];
                    unsigned b1 = Xs[(qcol + 4) * XS_STRIDE + xoff + 8 * j];
                    MMA_F16(acc[0][0][j], a00, b0, b1);
                    MMA_F16(acc[0][1][j], a01, b0, b1);
                    MMA_F16(acc[1][0][j], a10, b0, b1);
                    MMA_F16(acc[1][1][j], a11, b0, b1);
                }
            }
        }
    }

    // ---- epilogue: bias/sigmoid -> smem [sp 256][c pad36] -> float4 STG ----
    float* Ts = (float*)sm;            // 256*36 floats = 36864 B
    #pragma unroll
    for (int gi = 0; gi < 2; gi++) {
        const int g = g0 + gi, gate = g % 3, n = g / 3;
        const float* bptr = (gate == 0) ? bh : (gate == 1) ? bz : bs;
        float* og         = (gate == 0) ? g_hb : (gate == 1) ? g_z : g_s;
        __syncthreads();               // Xs/WF (and prev Ts reads) done
        #pragma unroll
        for (int f = 0; f < 2; f++) {
            #pragma unroll
            for (int part = 0; part < 2; part++) {
                int   co   = f * 16 + qrow + part * 8;
                float bias = bptr[n * 32 + co];
                #pragma unroll
                for (int j = 0; j < 4; j++) {
                    #pragma unroll
                    for (int wp = 0; wp < 2; wp++) {
                        float v = acc[gi][f][j][2 * part + wp] + bias;
                        if (gate > 0) v = 1.f / (1.f + __expf(-v));
                        int w = 8 * j + 2 * qcol + wp;
                        Ts[(wid * 32 + w) * 36 + co] = v;
                    }
                }
            }
        }
        __syncthreads();
        size_t obase = ((size_t)(n * 2 + b) << 20)
                     + (size_t)(d * 1024 + h0v * 32) * 32;
        #pragma unroll
        for (int e = 0; e < 8; e++) {
            int o = e * 1024 + tid * 4;
            int sp_loc = o >> 5, c = o & 31;
            float4 v4 = *(const float4*)(Ts + sp_loc * 36 + c);
            *(float4*)(og + obase + o) = v4;
        }
    }
}

// ---------------------------------------------------------------------------
// Scan: one WARP per diagonal chain, lane = channel. Layout [n][b][sp][c]:
// every step = 3 coalesced 128B loads + 1 coalesced store, L uniform per warp.
// 16 (n,b) x 2977 chains = 47632 warps = 5954 blocks x 8 warps.
// ---------------------------------------------------------------------------
__global__ void __launch_bounds__(256)
scan_kernel(const float* __restrict__ h0)
{
    const int gw   = blockIdx.x * 8 + (threadIdx.x >> 5);
    const int lane = threadIdx.x & 31;
    const int nb   = gw / 2977;
    const int cid  = gw % 2977;
    const int n = nb >> 1;

    const int di = (n & 4) ? 1 : -1;
    const int dj = (n & 2) ? 1 : -1;
    const int dk = (n & 1) ? 1 : -1;
    const int si = (di == 1) ? 0 : 31;
    const int sj = (dj == 1) ? 0 : 31;
    const int sk = (dk == 1) ? 0 : 31;

    int i0, j0, k0;
    if (cid < 1024) {                       // face i == si
        i0 = si; j0 = cid >> 5; k0 = cid & 31;
    } else if (cid < 2016) {                // face j == sj, i != si
        int q = cid - 1024;
        j0 = sj;
        int ii = q >> 5;
        i0 = (di == 1) ? ii + 1 : ii;
        k0 = q & 31;
    } else {                                // face k == sk, i != si, j != sj
        int q = cid - 2016;
        k0 = sk;
        int ii = q / 31;
        int jj = q % 31;
        i0 = (di == 1) ? ii + 1 : ii;
        j0 = (dj == 1) ? jj + 1 : jj;
    }

    int li = (di == 1) ? 32 - i0 : i0 + 1;
    int lj = (dj == 1) ? 32 - j0 : j0 + 1;
    int lk = (dk == 1) ? 32 - k0 : k0 + 1;
    int L  = min(li, min(lj, lk));

    const long long step = (long long)(di * 1024 + dj * 32 + dk) * 32;
    long long p = ((long long)nb << 20)
                + (long long)(i0 * 1024 + j0 * 32 + k0) * 32 + lane;

    float h = h0[n * 32 + lane];
    float zv = g_z[p], hv = g_hb[p], sv = g_s[p];
    for (int s = 0; s < L; s++) {
        long long pn = p + step;
        float zn = 0.f, hn = 0.f, sn = 0.f;
        if (s + 1 < L) { zn = g_z[pn]; hn = g_hb[pn]; sn = g_s[pn]; }
        h = fmaf(zv, hv - h, h);            // z*hb + (1-z)*h
        g_hb[p] = h * sv;                   // contrib, in place
        zv = zn; hv = hn; sv = sn; p = pn;
    }
}

// ---------------------------------------------------------------------------
// Combine: out[b][c][sp] = sum_n contrib[n][b][sp][c]; smem transpose.
// Grid: 2b x 128 sp-tiles of 256. Block 256 threads.
// FIX vs R14: first loop covers all 256 sp rows (e < 32, not e < 8).
// ---------------------------------------------------------------------------
__global__ void __launch_bounds__(256)
combine_kernel(float* __restrict__ out)
{
    __shared__ float Ts[256 * 33];
    const int b   = blockIdx.x >> 7;
    const int sp0 = (blockIdx.x & 127) * 256;
    const int tid = threadIdx.x;

    const int c_l  = tid & 31;
    const int sp_h = tid >> 5;          // 0..7
    #pragma unroll
    for (int e = 0; e < 32; e++) {      // 32*8 = 256 sp rows
        int sp_loc = e * 8 + sp_h;
        long long off = (long long)(sp0 + sp_loc) * 32 + c_l + ((long long)b << 20);
        float s = 0.f;
        #pragma unroll
        for (int n = 0; n < 8; n++)
            s += g_hb[((long long)n << 21) + off];
        Ts[sp_loc * 33 + c_l] = s;
    }
    __syncthreads();
    const int sp_l = tid & 31;
    const int c_h  = tid >> 5;          // 0..7
    #pragma unroll
    for (int chunk = 0; chunk < 8; chunk++) {
        int sp_loc = chunk * 32 + sp_l;
        #pragma unroll
        for (int ce = 0; ce < 4; ce++) {
            int c = ce * 8 + c_h;
            out[((size_t)(b * 32 + c) << 15) + sp0 + sp_loc] = Ts[sp_loc * 33 + c];
        }
    }
}

extern "C" void kernel_launch(void* const* d_in, const int* in_sizes, int n_in,
                              void* d_out, int out_size)
{
    const float* x  = (const float*)d_in[0];
    const float* Wh = (const float*)d_in[1];
    const float* bh = (const float*)d_in[2];
    const float* Wz = (const float*)d_in[3];
    const float* bz = (const float*)d_in[4];
    const float* Ws = (const float*)d_in[5];
    const float* bs = (const float*)d_in[6];
    const float* h0 = (const float*)d_in[7];
    float* out = (float*)d_out;

    cudaFuncSetAttribute(conv_mma2, cudaFuncAttributeMaxDynamicSharedMemorySize, SM_BYTES);

    prep_x<<<(B_ * C_ * SPAT + 255) / 256, 256>>>(x);
    prep_w<<<(24 * 2 * 3 * 9 * 256 + 255) / 256, 256>>>(Wh, Wz, Ws);
    conv_mma2<<<12 * 256, 256, SM_BYTES>>>(bh, bz, bs);
    scan_kernel<<<5954, 256>>>(h0);
    combine_kernel<<<256, 256>>>(out);
}